// round 15
// baseline (speedup 1.0000x reference)
#include <cuda_runtime.h>
#include <cuda_bf16.h>
#include <cstdint>

#define NMAX 100000
#define EMAX 3200000
#define BMAX 256
#define FIN  128
#define HDIM 64

// Scratch (device globals).
__device__ __align__(16) __nv_bfloat16 g_h1[NMAX * HDIM];  // unscaled x@W1, bf16
__device__ __align__(16) __nv_bfloat16 g_h2[NMAX * HDIM];  // h2' (scaled), bf16
__device__ float g_dinv[NMAX];
__device__ __align__(16) float g_sums[BMAX * HDIM];
__device__ float g_cnt[BMAX];
// CSR-by-dst
__device__ int g_hist[NMAX];
__device__ int g_off[NMAX + 1];
__device__ int g_pos[NMAX];
__device__ int g_ssrc[EMAX];
__device__ int g_blocksum[512];

// bf16x4 <-> float4 helpers (8-byte packets)
__device__ __forceinline__ uint2 pack_bf4(float a, float b, float c, float d) {
    __nv_bfloat162 p0 = __floats2bfloat162_rn(a, b);
    __nv_bfloat162 p1 = __floats2bfloat162_rn(c, d);
    uint2 u;
    u.x = *reinterpret_cast<uint32_t*>(&p0);
    u.y = *reinterpret_cast<uint32_t*>(&p1);
    return u;
}
__device__ __forceinline__ float4 unpack_bf4(uint2 u) {
    __nv_bfloat162 p0 = *reinterpret_cast<__nv_bfloat162*>(&u.x);
    __nv_bfloat162 p1 = *reinterpret_cast<__nv_bfloat162*>(&u.y);
    float2 f0 = __bfloat1622float2(p0);
    float2 f1 = __bfloat1622float2(p1);
    return make_float4(f0.x, f0.y, f1.x, f1.y);
}

// ---------------------------------------------------------------- init
__global__ void init_kernel(int n, int b) {
    int i = blockIdx.x * blockDim.x + threadIdx.x;
    if (i < n) g_hist[i] = 0;
    if (i < b * HDIM) g_sums[i] = 0.0f;
    if (i < b) g_cnt[i] = 0.0f;
}

// --------------------------------------------------- histogram of dst
__global__ void hist_kernel(const int* __restrict__ ei, int e_cnt) {
    int e = blockIdx.x * blockDim.x + threadIdx.x;
    if (e >= e_cnt) return;
    atomicAdd(&g_hist[ei[e_cnt + e]], 1);
}

// --------------------------------------------------- scan A
__global__ void scanA_kernel(int n) {
    __shared__ int s[256];
    int tid = threadIdx.x;
    int i = blockIdx.x * 256 + tid;
    int cnt = (i < n) ? g_hist[i] : 0;
    s[tid] = cnt;
    __syncthreads();
#pragma unroll
    for (int ofs = 1; ofs < 256; ofs <<= 1) {
        int v = (tid >= ofs) ? s[tid - ofs] : 0;
        __syncthreads();
        s[tid] += v;
        __syncthreads();
    }
    if (i < n) g_off[i] = s[tid] - cnt;
    if (tid == 255) g_blocksum[blockIdx.x] = s[255];
}

// --------------------------------------------------- scan B
__global__ void scanB_kernel(int nb) {
    __shared__ int s[512];
    int tid = threadIdx.x;
    int v = (tid < nb) ? g_blocksum[tid] : 0;
    s[tid] = v;
    __syncthreads();
#pragma unroll
    for (int ofs = 1; ofs < 512; ofs <<= 1) {
        int u = (tid >= ofs) ? s[tid - ofs] : 0;
        __syncthreads();
        s[tid] += u;
        __syncthreads();
    }
    if (tid < nb) g_blocksum[tid] = s[tid] - v;
}

// --------------------------------------------------- scan C: offsets + cursor + dinv + graph counts
__global__ void scanC_kernel(const int* __restrict__ batch, int n, int e_cnt) {
    int i = blockIdx.x * blockDim.x + threadIdx.x;
    if (i >= n) return;
    int o = g_off[i] + g_blocksum[i >> 8];
    g_off[i] = o;
    g_pos[i] = o;
    if (i == n - 1) g_off[n] = e_cnt;
    g_dinv[i] = rsqrtf((float)(g_hist[i] + 1));
    atomicAdd(&g_cnt[batch[i]], 1.0f);
}

// --------------------------------------------------- place edges into CSR
__global__ void place_kernel(const int* __restrict__ ei, int e_cnt) {
    int e = blockIdx.x * blockDim.x + threadIdx.x;
    if (e >= e_cnt) return;
    int s = ei[e];
    int d = ei[e_cnt + e];
    int p = atomicAdd(&g_pos[d], 1);
    g_ssrc[p] = s;
}

// --------------------------------------------------- GEMM1: g_h1 = x @ W1  (UNSCALED, bf16)
#define G1_BM 128
#define G1_BK 16
__global__ __launch_bounds__(256) void gemm1_kernel(const float* __restrict__ x,
                                                    const float* __restrict__ W1, int n) {
    __shared__ float ws[FIN * HDIM];
    __shared__ float xs[G1_BK][G1_BM];
    int tid = threadIdx.x;
    for (int i = tid; i < FIN * HDIM / 4; i += 256)
        reinterpret_cast<float4*>(ws)[i] = reinterpret_cast<const float4*>(W1)[i];
    int tx = tid & 15;
    int ty = tid >> 4;
    int row0 = blockIdx.x * G1_BM;
    float acc[8][4] = {};
    for (int k0 = 0; k0 < FIN; k0 += G1_BK) {
        __syncthreads();
#pragma unroll
        for (int l = 0; l < 2; l++) {
            int idx = tid * 2 + l;
            int r = idx >> 2;
            int kq = idx & 3;
            int grow = row0 + r;
            float4 v = (grow < n)
                ? reinterpret_cast<const float4*>(x + (size_t)grow * FIN + k0)[kq]
                : make_float4(0.f, 0.f, 0.f, 0.f);
            xs[kq * 4 + 0][r] = v.x;
            xs[kq * 4 + 1][r] = v.y;
            xs[kq * 4 + 2][r] = v.z;
            xs[kq * 4 + 3][r] = v.w;
        }
        __syncthreads();
#pragma unroll
        for (int k = 0; k < G1_BK; k++) {
            float4 wv = reinterpret_cast<const float4*>(ws + (k0 + k) * HDIM)[tx];
            float4 xa = *reinterpret_cast<const float4*>(&xs[k][ty * 8]);
            float4 xb = *reinterpret_cast<const float4*>(&xs[k][ty * 8 + 4]);
            float xv[8] = {xa.x, xa.y, xa.z, xa.w, xb.x, xb.y, xb.z, xb.w};
#pragma unroll
            for (int i = 0; i < 8; i++) {
                acc[i][0] = fmaf(xv[i], wv.x, acc[i][0]);
                acc[i][1] = fmaf(xv[i], wv.y, acc[i][1]);
                acc[i][2] = fmaf(xv[i], wv.z, acc[i][2]);
                acc[i][3] = fmaf(xv[i], wv.w, acc[i][3]);
            }
        }
    }
#pragma unroll
    for (int i = 0; i < 8; i++) {
        int row = row0 + ty * 8 + i;
        if (row >= n) break;
        uint2 u = pack_bf4(acc[i][0], acc[i][1], acc[i][2], acc[i][3]);
        reinterpret_cast<uint2*>(g_h1)[(size_t)row * 16 + tx] = u;
    }
}

// --------------------------------------------------- FUSED gather1 + gemm2:
// For each row d of the block's 128-row tile:
//   acc1[d] = dinv[d]*h1[d] + sum_{s->d} dinv[s]*h1[s]   (bf16 gather, fp32 acc)
//   z[d]    = relu(dinv[d]*acc1[d] + b1)      -> smem (transposed)
//   h2'[d]  = (z @ W2) * dinv[d]              -> g_h2 (bf16)
#define G2_BM 128
__global__ __launch_bounds__(256) void gather1_gemm2_kernel(const float* __restrict__ W2,
                                                            const float* __restrict__ b1, int n) {
    __shared__ float ws[HDIM * HDIM];          // [k][c]   16KB
    __shared__ float zs[HDIM][G2_BM];          // [k][row] 32KB
    int tid = threadIdx.x;
    for (int i = tid; i < HDIM * HDIM / 4; i += 256)
        reinterpret_cast<float4*>(ws)[i] = reinterpret_cast<const float4*>(W2)[i];
    int row0 = blockIdx.x * G2_BM;
    const uint2* h = reinterpret_cast<const uint2*>(g_h1);

    // Phase A: gather + relu, 2048 (row, slice) tasks over 256 threads (8 each).
#pragma unroll
    for (int t8 = 0; t8 < 8; t8++) {
        int task = t8 * 256 + tid;           // 0..2047
        int r = task >> 4;                   // 0..127
        int j = task & 15;                   // 8B slice (4 cols)
        int d = row0 + r;
        float4 z = make_float4(0.f, 0.f, 0.f, 0.f);
        if (d < n) {
            float did = g_dinv[d];
            float4 hv = unpack_bf4(__ldg(&h[(size_t)d * 16 + j]));
            float4 acc = make_float4(did * hv.x, did * hv.y, did * hv.z, did * hv.w);
            int k = g_off[d], end = g_off[d + 1];
            for (; k + 8 <= end; k += 8) {
                int s0 = g_ssrc[k + 0], s1 = g_ssrc[k + 1], s2 = g_ssrc[k + 2], s3 = g_ssrc[k + 3];
                int s4 = g_ssrc[k + 4], s5 = g_ssrc[k + 5], s6 = g_ssrc[k + 6], s7 = g_ssrc[k + 7];
                float4 v0 = unpack_bf4(__ldg(&h[(size_t)s0 * 16 + j]));
                float4 v1 = unpack_bf4(__ldg(&h[(size_t)s1 * 16 + j]));
                float4 v2 = unpack_bf4(__ldg(&h[(size_t)s2 * 16 + j]));
                float4 v3 = unpack_bf4(__ldg(&h[(size_t)s3 * 16 + j]));
                float4 v4 = unpack_bf4(__ldg(&h[(size_t)s4 * 16 + j]));
                float4 v5 = unpack_bf4(__ldg(&h[(size_t)s5 * 16 + j]));
                float4 v6 = unpack_bf4(__ldg(&h[(size_t)s6 * 16 + j]));
                float4 v7 = unpack_bf4(__ldg(&h[(size_t)s7 * 16 + j]));
                float di0 = __ldg(&g_dinv[s0]), di1 = __ldg(&g_dinv[s1]);
                float di2 = __ldg(&g_dinv[s2]), di3 = __ldg(&g_dinv[s3]);
                float di4 = __ldg(&g_dinv[s4]), di5 = __ldg(&g_dinv[s5]);
                float di6 = __ldg(&g_dinv[s6]), di7 = __ldg(&g_dinv[s7]);
                acc.x = fmaf(di0, v0.x, fmaf(di1, v1.x, fmaf(di2, v2.x, fmaf(di3, v3.x, acc.x))));
                acc.x = fmaf(di4, v4.x, fmaf(di5, v5.x, fmaf(di6, v6.x, fmaf(di7, v7.x, acc.x))));
                acc.y = fmaf(di0, v0.y, fmaf(di1, v1.y, fmaf(di2, v2.y, fmaf(di3, v3.y, acc.y))));
                acc.y = fmaf(di4, v4.y, fmaf(di5, v5.y, fmaf(di6, v6.y, fmaf(di7, v7.y, acc.y))));
                acc.z = fmaf(di0, v0.z, fmaf(di1, v1.z, fmaf(di2, v2.z, fmaf(di3, v3.z, acc.z))));
                acc.z = fmaf(di4, v4.z, fmaf(di5, v5.z, fmaf(di6, v6.z, fmaf(di7, v7.z, acc.z))));
                acc.w = fmaf(di0, v0.w, fmaf(di1, v1.w, fmaf(di2, v2.w, fmaf(di3, v3.w, acc.w))));
                acc.w = fmaf(di4, v4.w, fmaf(di5, v5.w, fmaf(di6, v6.w, fmaf(di7, v7.w, acc.w))));
            }
            for (; k < end; k++) {
                int s = g_ssrc[k];
                float di = __ldg(&g_dinv[s]);
                float4 v = unpack_bf4(__ldg(&h[(size_t)s * 16 + j]));
                acc.x = fmaf(di, v.x, acc.x);
                acc.y = fmaf(di, v.y, acc.y);
                acc.z = fmaf(di, v.z, acc.z);
                acc.w = fmaf(di, v.w, acc.w);
            }
            z.x = fmaxf(fmaf(did, acc.x, b1[j * 4 + 0]), 0.f);
            z.y = fmaxf(fmaf(did, acc.y, b1[j * 4 + 1]), 0.f);
            z.z = fmaxf(fmaf(did, acc.z, b1[j * 4 + 2]), 0.f);
            z.w = fmaxf(fmaf(did, acc.w, b1[j * 4 + 3]), 0.f);
        }
        zs[j * 4 + 0][r] = z.x;
        zs[j * 4 + 1][r] = z.y;
        zs[j * 4 + 2][r] = z.z;
        zs[j * 4 + 3][r] = z.w;
    }
    __syncthreads();

    // Phase B: register-tiled GEMM (z @ W2) * dinv -> g_h2 bf16
    int tx = tid & 15;
    int ty = tid >> 4;
    float acc[8][4] = {};
#pragma unroll
    for (int k = 0; k < HDIM; k++) {
        float4 wv = reinterpret_cast<const float4*>(ws + k * HDIM)[tx];
        float4 xa = *reinterpret_cast<const float4*>(&zs[k][ty * 8]);
        float4 xb = *reinterpret_cast<const float4*>(&zs[k][ty * 8 + 4]);
        float xv[8] = {xa.x, xa.y, xa.z, xa.w, xb.x, xb.y, xb.z, xb.w};
#pragma unroll
        for (int i = 0; i < 8; i++) {
            acc[i][0] = fmaf(xv[i], wv.x, acc[i][0]);
            acc[i][1] = fmaf(xv[i], wv.y, acc[i][1]);
            acc[i][2] = fmaf(xv[i], wv.z, acc[i][2]);
            acc[i][3] = fmaf(xv[i], wv.w, acc[i][3]);
        }
    }
#pragma unroll
    for (int i = 0; i < 8; i++) {
        int row = row0 + ty * 8 + i;
        if (row >= n) break;
        float di = g_dinv[row];
        uint2 u = pack_bf4(acc[i][0] * di, acc[i][1] * di, acc[i][2] * di, acc[i][3] * di);
        reinterpret_cast<uint2*>(g_h2)[(size_t)row * 16 + tx] = u;
    }
}

// --------------------------------------------------- gather2 + pool fused (unroll 8):
__global__ void gather2_pool_kernel(const float* __restrict__ b2,
                                    const int* __restrict__ batch, int n) {
    int t = blockIdx.x * blockDim.x + threadIdx.x;
    int d = t >> 4;
    if (d >= n) return;
    int j = t & 15;
    const uint2* h = reinterpret_cast<const uint2*>(g_h2);
    float4 acc = unpack_bf4(__ldg(&h[(size_t)d * 16 + j]));     // self loop
    int k = g_off[d], end = g_off[d + 1];
    for (; k + 8 <= end; k += 8) {
        int s0 = g_ssrc[k + 0], s1 = g_ssrc[k + 1], s2 = g_ssrc[k + 2], s3 = g_ssrc[k + 3];
        int s4 = g_ssrc[k + 4], s5 = g_ssrc[k + 5], s6 = g_ssrc[k + 6], s7 = g_ssrc[k + 7];
        float4 v0 = unpack_bf4(__ldg(&h[(size_t)s0 * 16 + j]));
        float4 v1 = unpack_bf4(__ldg(&h[(size_t)s1 * 16 + j]));
        float4 v2 = unpack_bf4(__ldg(&h[(size_t)s2 * 16 + j]));
        float4 v3 = unpack_bf4(__ldg(&h[(size_t)s3 * 16 + j]));
        float4 v4 = unpack_bf4(__ldg(&h[(size_t)s4 * 16 + j]));
        float4 v5 = unpack_bf4(__ldg(&h[(size_t)s5 * 16 + j]));
        float4 v6 = unpack_bf4(__ldg(&h[(size_t)s6 * 16 + j]));
        float4 v7 = unpack_bf4(__ldg(&h[(size_t)s7 * 16 + j]));
        acc.x += ((v0.x + v1.x) + (v2.x + v3.x)) + ((v4.x + v5.x) + (v6.x + v7.x));
        acc.y += ((v0.y + v1.y) + (v2.y + v3.y)) + ((v4.y + v5.y) + (v6.y + v7.y));
        acc.z += ((v0.z + v1.z) + (v2.z + v3.z)) + ((v4.z + v5.z) + (v6.z + v7.z));
        acc.w += ((v0.w + v1.w) + (v2.w + v3.w)) + ((v4.w + v5.w) + (v6.w + v7.w));
    }
    for (; k < end; k++) {
        int s = g_ssrc[k];
        float4 v = unpack_bf4(__ldg(&h[(size_t)s * 16 + j]));
        acc.x += v.x; acc.y += v.y; acc.z += v.z; acc.w += v.w;
    }
    float di = g_dinv[d];
    float4 bb = make_float4(b2[j * 4 + 0], b2[j * 4 + 1], b2[j * 4 + 2], b2[j * 4 + 3]);
    float4 y;
    y.x = fmaxf(fmaf(di, acc.x, bb.x), 0.0f);
    y.y = fmaxf(fmaf(di, acc.y, bb.y), 0.0f);
    y.z = fmaxf(fmaf(di, acc.z, bb.z), 0.0f);
    y.w = fmaxf(fmaf(di, acc.w, bb.w), 0.0f);
    float* p = g_sums + (size_t)batch[d] * HDIM + j * 4;
    asm volatile(
        "{\n\t"
        ".reg .u64 ga;\n\t"
        "cvta.to.global.u64 ga, %0;\n\t"
        "red.global.add.v4.f32 [ga], {%1, %2, %3, %4};\n\t"
        "}"
        :: "l"(p), "f"(y.x), "f"(y.y), "f"(y.z), "f"(y.w) : "memory");
}

// --------------------------------------------------- final
__global__ void final_kernel(const float* __restrict__ Wl, const float* __restrict__ bl,
                             float* __restrict__ out, int b_cnt) {
    int t = blockIdx.x * blockDim.x + threadIdx.x;
    if (t >= b_cnt * 2) return;
    int b = t >> 1, c = t & 1;
    float cnt = fmaxf(g_cnt[b], 1.0f);
    float acc = 0.0f;
#pragma unroll
    for (int k = 0; k < HDIM; k++) acc = fmaf(g_sums[b * HDIM + k], Wl[k * 2 + c], acc);
    out[b * 2 + c] = acc / cnt + bl[c];
}

// ====================================================================
extern "C" void kernel_launch(void* const* d_in, const int* in_sizes, int n_in,
                              void* d_out, int out_size) {
    const float* x     = (const float*)d_in[0];
    const int*   ei    = (const int*)d_in[1];
    const int*   batch = (const int*)d_in[2];
    const float* W1    = (const float*)d_in[3];
    const float* b1    = (const float*)d_in[4];
    const float* W2    = (const float*)d_in[5];
    const float* b2    = (const float*)d_in[6];
    const float* Wl    = (const float*)d_in[7];
    const float* bl    = (const float*)d_in[8];
    float* out = (float*)d_out;

    int n = in_sizes[0] / FIN;        // 100000
    int e = in_sizes[1] / 2;          // 3200000
    int b = out_size / 2;             // 256
    int nb = (n + 255) / 256;

    // One-time host-side stream/event setup (no device memory involved).
    static cudaStream_t s_side = nullptr;
    static cudaEvent_t ev_fork = nullptr, ev_join = nullptr;
    if (s_side == nullptr) {
        cudaStreamCreateWithFlags(&s_side, cudaStreamNonBlocking);
        cudaEventCreateWithFlags(&ev_fork, cudaEventDisableTiming);
        cudaEventCreateWithFlags(&ev_join, cudaEventDisableTiming);
    }

    // Fork: CSR prep chain on side stream; gemm1 (dinv-free) on main stream.
    cudaEventRecord(ev_fork, 0);
    cudaStreamWaitEvent(s_side, ev_fork, 0);

    init_kernel<<<(n + 255) / 256, 256, 0, s_side>>>(n, b);
    hist_kernel<<<(e + 255) / 256, 256, 0, s_side>>>(ei, e);
    scanA_kernel<<<nb, 256, 0, s_side>>>(n);
    scanB_kernel<<<1, 512, 0, s_side>>>(nb);
    scanC_kernel<<<nb, 256, 0, s_side>>>(batch, n, e);
    place_kernel<<<(e + 255) / 256, 256, 0, s_side>>>(ei, e);
    cudaEventRecord(ev_join, s_side);

    // gemm1 reads only x and W1 — no dependency on the side stream.
    gemm1_kernel<<<(n + G1_BM - 1) / G1_BM, 256>>>(x, W1, n);

    // Join: everything after needs CSR + dinv.
    cudaStreamWaitEvent(0, ev_join, 0);
    gather1_gemm2_kernel<<<(n + G2_BM - 1) / G2_BM, 256>>>(W2, b1, n);
    {
        long long threads = (long long)n * 16;
        gather2_pool_kernel<<<(int)((threads + 255) / 256), 256>>>(b2, batch, n);
    }
    final_kernel<<<(b * 2 + 255) / 256, 256>>>(Wl, bl, out, b);
}

// round 17
// speedup vs baseline: 1.0522x; 1.0522x over previous
#include <cuda_runtime.h>
#include <cuda_bf16.h>
#include <cstdint>

#define NMAX 100000
#define EMAX 3200000
#define BMAX 256
#define FIN  128
#define HDIM 64

// Scratch (device globals).
__device__ __align__(16) __nv_bfloat16 g_h1[NMAX * HDIM];  // x@W1, then scaled in place by dinv
__device__ __align__(16) __nv_bfloat16 g_h2[NMAX * HDIM];  // h2' (scaled), bf16
__device__ __align__(16) float g_acc1[NMAX * HDIM];        // gather1 output, fp32
__device__ float g_dinv[NMAX];
__device__ __align__(16) float g_sums[BMAX * HDIM];
__device__ float g_cnt[BMAX];
// CSR-by-dst
__device__ int g_hist[NMAX];
__device__ int g_off[NMAX + 1];
__device__ int g_pos[NMAX];
__device__ __align__(16) int g_ssrc[EMAX];
__device__ int g_blocksum[512];

// ---- bf16 helpers ----
__device__ __forceinline__ uint2 pack_bf4(float a, float b, float c, float d) {
    __nv_bfloat162 p0 = __floats2bfloat162_rn(a, b);
    __nv_bfloat162 p1 = __floats2bfloat162_rn(c, d);
    uint2 u;
    u.x = *reinterpret_cast<uint32_t*>(&p0);
    u.y = *reinterpret_cast<uint32_t*>(&p1);
    return u;
}
__device__ __forceinline__ void unpack_bf8(uint4 u, float* f) {
    __nv_bfloat162 p0 = *reinterpret_cast<__nv_bfloat162*>(&u.x);
    __nv_bfloat162 p1 = *reinterpret_cast<__nv_bfloat162*>(&u.y);
    __nv_bfloat162 p2 = *reinterpret_cast<__nv_bfloat162*>(&u.z);
    __nv_bfloat162 p3 = *reinterpret_cast<__nv_bfloat162*>(&u.w);
    float2 a = __bfloat1622float2(p0), b = __bfloat1622float2(p1);
    float2 c = __bfloat1622float2(p2), d = __bfloat1622float2(p3);
    f[0] = a.x; f[1] = a.y; f[2] = b.x; f[3] = b.y;
    f[4] = c.x; f[5] = c.y; f[6] = d.x; f[7] = d.y;
}
__device__ __forceinline__ uint4 pack_bf8(const float* f) {
    uint4 u;
    __nv_bfloat162 p0 = __floats2bfloat162_rn(f[0], f[1]);
    __nv_bfloat162 p1 = __floats2bfloat162_rn(f[2], f[3]);
    __nv_bfloat162 p2 = __floats2bfloat162_rn(f[4], f[5]);
    __nv_bfloat162 p3 = __floats2bfloat162_rn(f[6], f[7]);
    u.x = *reinterpret_cast<uint32_t*>(&p0);
    u.y = *reinterpret_cast<uint32_t*>(&p1);
    u.z = *reinterpret_cast<uint32_t*>(&p2);
    u.w = *reinterpret_cast<uint32_t*>(&p3);
    return u;
}
__device__ __forceinline__ void acc_bf8(float* acc, uint4 u) {
    float f[8];
    unpack_bf8(u, f);
#pragma unroll
    for (int i = 0; i < 8; i++) acc[i] += f[i];
}

// ---------------------------------------------------------------- init
__global__ void init_kernel(int n, int b) {
    int i = blockIdx.x * blockDim.x + threadIdx.x;
    if (i < n) g_hist[i] = 0;
    if (i < b * HDIM) g_sums[i] = 0.0f;
    if (i < b) g_cnt[i] = 0.0f;
}

// --------------------------------------------------- histogram of dst
__global__ void hist_kernel(const int* __restrict__ ei, int e_cnt) {
    int e = blockIdx.x * blockDim.x + threadIdx.x;
    if (e >= e_cnt) return;
    atomicAdd(&g_hist[ei[e_cnt + e]], 1);
}

// --------------------------------------------------- scan A
__global__ void scanA_kernel(int n) {
    __shared__ int s[256];
    int tid = threadIdx.x;
    int i = blockIdx.x * 256 + tid;
    int cnt = (i < n) ? g_hist[i] : 0;
    s[tid] = cnt;
    __syncthreads();
#pragma unroll
    for (int ofs = 1; ofs < 256; ofs <<= 1) {
        int v = (tid >= ofs) ? s[tid - ofs] : 0;
        __syncthreads();
        s[tid] += v;
        __syncthreads();
    }
    if (i < n) g_off[i] = s[tid] - cnt;
    if (tid == 255) g_blocksum[blockIdx.x] = s[255];
}

// --------------------------------------------------- scan B
__global__ void scanB_kernel(int nb) {
    __shared__ int s[512];
    int tid = threadIdx.x;
    int v = (tid < nb) ? g_blocksum[tid] : 0;
    s[tid] = v;
    __syncthreads();
#pragma unroll
    for (int ofs = 1; ofs < 512; ofs <<= 1) {
        int u = (tid >= ofs) ? s[tid - ofs] : 0;
        __syncthreads();
        s[tid] += u;
        __syncthreads();
    }
    if (tid < nb) g_blocksum[tid] = s[tid] - v;
}

// --------------------------------------------------- scan C
__global__ void scanC_kernel(const int* __restrict__ batch, int n, int e_cnt) {
    int i = blockIdx.x * blockDim.x + threadIdx.x;
    if (i >= n) return;
    int o = g_off[i] + g_blocksum[i >> 8];
    g_off[i] = o;
    g_pos[i] = o;
    if (i == n - 1) g_off[n] = e_cnt;
    g_dinv[i] = rsqrtf((float)(g_hist[i] + 1));
    atomicAdd(&g_cnt[batch[i]], 1.0f);
}

// --------------------------------------------------- place edges into CSR
__global__ void place_kernel(const int* __restrict__ ei, int e_cnt) {
    int e = blockIdx.x * blockDim.x + threadIdx.x;
    if (e >= e_cnt) return;
    int s = ei[e];
    int d = ei[e_cnt + e];
    int p = atomicAdd(&g_pos[d], 1);
    g_ssrc[p] = s;
}

// --------------------------------------------------- GEMM1: g_h1 = x @ W1  (UNSCALED, bf16)
#define G1_BM 128
#define G1_BK 16
__global__ __launch_bounds__(256) void gemm1_kernel(const float* __restrict__ x,
                                                    const float* __restrict__ W1, int n) {
    __shared__ float ws[FIN * HDIM];
    __shared__ float xs[G1_BK][G1_BM];
    int tid = threadIdx.x;
    for (int i = tid; i < FIN * HDIM / 4; i += 256)
        reinterpret_cast<float4*>(ws)[i] = reinterpret_cast<const float4*>(W1)[i];
    int tx = tid & 15;
    int ty = tid >> 4;
    int row0 = blockIdx.x * G1_BM;
    float acc[8][4] = {};
    for (int k0 = 0; k0 < FIN; k0 += G1_BK) {
        __syncthreads();
#pragma unroll
        for (int l = 0; l < 2; l++) {
            int idx = tid * 2 + l;
            int r = idx >> 2;
            int kq = idx & 3;
            int grow = row0 + r;
            float4 v = (grow < n)
                ? reinterpret_cast<const float4*>(x + (size_t)grow * FIN + k0)[kq]
                : make_float4(0.f, 0.f, 0.f, 0.f);
            xs[kq * 4 + 0][r] = v.x;
            xs[kq * 4 + 1][r] = v.y;
            xs[kq * 4 + 2][r] = v.z;
            xs[kq * 4 + 3][r] = v.w;
        }
        __syncthreads();
#pragma unroll
        for (int k = 0; k < G1_BK; k++) {
            float4 wv = reinterpret_cast<const float4*>(ws + (k0 + k) * HDIM)[tx];
            float4 xa = *reinterpret_cast<const float4*>(&xs[k][ty * 8]);
            float4 xb = *reinterpret_cast<const float4*>(&xs[k][ty * 8 + 4]);
            float xv[8] = {xa.x, xa.y, xa.z, xa.w, xb.x, xb.y, xb.z, xb.w};
#pragma unroll
            for (int i = 0; i < 8; i++) {
                acc[i][0] = fmaf(xv[i], wv.x, acc[i][0]);
                acc[i][1] = fmaf(xv[i], wv.y, acc[i][1]);
                acc[i][2] = fmaf(xv[i], wv.z, acc[i][2]);
                acc[i][3] = fmaf(xv[i], wv.w, acc[i][3]);
            }
        }
    }
#pragma unroll
    for (int i = 0; i < 8; i++) {
        int row = row0 + ty * 8 + i;
        if (row >= n) break;
        uint2 u = pack_bf4(acc[i][0], acc[i][1], acc[i][2], acc[i][3]);
        reinterpret_cast<uint2*>(g_h1)[(size_t)row * 16 + tx] = u;
    }
}

// --------------------------------------------------- scale h1 in place: h1[row] *= dinv[row]
__global__ void scale_h1_kernel(int n) {
    int t = blockIdx.x * blockDim.x + threadIdx.x;
    int row = t >> 3;
    if (row >= n) return;
    int j = t & 7;
    uint4* h = reinterpret_cast<uint4*>(g_h1);
    float f[8];
    unpack_bf8(h[(size_t)row * 8 + j], f);
    float di = g_dinv[row];
#pragma unroll
    for (int i = 0; i < 8; i++) f[i] *= di;
    h[(size_t)row * 8 + j] = pack_bf8(f);
}

// --------------------------------------------------- gather1: acc1[d] = h1s[d] + sum h1s[src]
// 8 lanes/dst, uint4 (16B) h loads, int4 ssrc loads with alignment peel.
__global__ void gather1_kernel(int n) {
    int t = blockIdx.x * blockDim.x + threadIdx.x;
    int d = t >> 3;
    if (d >= n) return;
    int j = t & 7;
    const uint4* h = reinterpret_cast<const uint4*>(g_h1);
    float acc[8];
    unpack_bf8(__ldg(&h[(size_t)d * 8 + j]), acc);      // self term (pre-scaled)
    int k = g_off[d], end = g_off[d + 1];
    // peel to int4 alignment
    for (; k < end && (k & 3); k++)
        acc_bf8(acc, __ldg(&h[(size_t)g_ssrc[k] * 8 + j]));
    // main: 8 edges per iter (2 x int4 ssrc, 8 x uint4 h)
    for (; k + 8 <= end; k += 8) {
        int4 sa = *reinterpret_cast<const int4*>(g_ssrc + k);
        int4 sb = *reinterpret_cast<const int4*>(g_ssrc + k + 4);
        uint4 u0 = __ldg(&h[(size_t)sa.x * 8 + j]);
        uint4 u1 = __ldg(&h[(size_t)sa.y * 8 + j]);
        uint4 u2 = __ldg(&h[(size_t)sa.z * 8 + j]);
        uint4 u3 = __ldg(&h[(size_t)sa.w * 8 + j]);
        uint4 u4 = __ldg(&h[(size_t)sb.x * 8 + j]);
        uint4 u5 = __ldg(&h[(size_t)sb.y * 8 + j]);
        uint4 u6 = __ldg(&h[(size_t)sb.z * 8 + j]);
        uint4 u7 = __ldg(&h[(size_t)sb.w * 8 + j]);
        acc_bf8(acc, u0); acc_bf8(acc, u1); acc_bf8(acc, u2); acc_bf8(acc, u3);
        acc_bf8(acc, u4); acc_bf8(acc, u5); acc_bf8(acc, u6); acc_bf8(acc, u7);
    }
    for (; k + 4 <= end; k += 4) {
        int4 sa = *reinterpret_cast<const int4*>(g_ssrc + k);
        uint4 u0 = __ldg(&h[(size_t)sa.x * 8 + j]);
        uint4 u1 = __ldg(&h[(size_t)sa.y * 8 + j]);
        uint4 u2 = __ldg(&h[(size_t)sa.z * 8 + j]);
        uint4 u3 = __ldg(&h[(size_t)sa.w * 8 + j]);
        acc_bf8(acc, u0); acc_bf8(acc, u1); acc_bf8(acc, u2); acc_bf8(acc, u3);
    }
    for (; k < end; k++)
        acc_bf8(acc, __ldg(&h[(size_t)g_ssrc[k] * 8 + j]));
    float4* o = reinterpret_cast<float4*>(g_acc1 + (size_t)d * HDIM + j * 8);
    o[0] = make_float4(acc[0], acc[1], acc[2], acc[3]);
    o[1] = make_float4(acc[4], acc[5], acc[6], acc[7]);
}

// --------------------------------------------------- GEMM2 fused:
// z = relu(dinv*acc1 + b1); h2' = (z @ W2) * dinv  -> g_h2 (bf16)
#define G2_BM 128
__global__ __launch_bounds__(256) void gemm2_kernel(const float* __restrict__ W2,
                                                    const float* __restrict__ b1, int n) {
    __shared__ float ws[HDIM * HDIM];
    __shared__ float zs[HDIM][G2_BM];
    int tid = threadIdx.x;
    for (int i = tid; i < HDIM * HDIM / 4; i += 256)
        reinterpret_cast<float4*>(ws)[i] = reinterpret_cast<const float4*>(W2)[i];
    int row0 = blockIdx.x * G2_BM;
#pragma unroll
    for (int l = 0; l < 8; l++) {
        int idx = tid * 8 + l;
        int r = idx >> 4;
        int cq = idx & 15;
        int grow = row0 + r;
        float4 v = make_float4(0.f, 0.f, 0.f, 0.f);
        if (grow < n) {
            float di = g_dinv[grow];
            float4 a = reinterpret_cast<const float4*>(g_acc1 + (size_t)grow * HDIM)[cq];
            v.x = fmaxf(fmaf(di, a.x, b1[cq * 4 + 0]), 0.f);
            v.y = fmaxf(fmaf(di, a.y, b1[cq * 4 + 1]), 0.f);
            v.z = fmaxf(fmaf(di, a.z, b1[cq * 4 + 2]), 0.f);
            v.w = fmaxf(fmaf(di, a.w, b1[cq * 4 + 3]), 0.f);
        }
        zs[cq * 4 + 0][r] = v.x;
        zs[cq * 4 + 1][r] = v.y;
        zs[cq * 4 + 2][r] = v.z;
        zs[cq * 4 + 3][r] = v.w;
    }
    __syncthreads();
    int tx = tid & 15;
    int ty = tid >> 4;
    float acc[8][4] = {};
#pragma unroll
    for (int k = 0; k < HDIM; k++) {
        float4 wv = reinterpret_cast<const float4*>(ws + k * HDIM)[tx];
        float4 xa = *reinterpret_cast<const float4*>(&zs[k][ty * 8]);
        float4 xb = *reinterpret_cast<const float4*>(&zs[k][ty * 8 + 4]);
        float xv[8] = {xa.x, xa.y, xa.z, xa.w, xb.x, xb.y, xb.z, xb.w};
#pragma unroll
        for (int i = 0; i < 8; i++) {
            acc[i][0] = fmaf(xv[i], wv.x, acc[i][0]);
            acc[i][1] = fmaf(xv[i], wv.y, acc[i][1]);
            acc[i][2] = fmaf(xv[i], wv.z, acc[i][2]);
            acc[i][3] = fmaf(xv[i], wv.w, acc[i][3]);
        }
    }
#pragma unroll
    for (int i = 0; i < 8; i++) {
        int row = row0 + ty * 8 + i;
        if (row >= n) break;
        float di = g_dinv[row];
        uint2 u = pack_bf4(acc[i][0] * di, acc[i][1] * di, acc[i][2] * di, acc[i][3] * di);
        reinterpret_cast<uint2*>(g_h2)[(size_t)row * 16 + tx] = u;   // h2' (scaled)
    }
}

// --------------------------------------------------- gather2 + pool fused (8 lanes/dst):
__global__ void gather2_pool_kernel(const float* __restrict__ b2,
                                    const int* __restrict__ batch, int n) {
    int t = blockIdx.x * blockDim.x + threadIdx.x;
    int d = t >> 3;
    if (d >= n) return;
    int j = t & 7;
    const uint4* h = reinterpret_cast<const uint4*>(g_h2);
    float acc[8];
    unpack_bf8(__ldg(&h[(size_t)d * 8 + j]), acc);      // self term
    int k = g_off[d], end = g_off[d + 1];
    for (; k < end && (k & 3); k++)
        acc_bf8(acc, __ldg(&h[(size_t)g_ssrc[k] * 8 + j]));
    for (; k + 8 <= end; k += 8) {
        int4 sa = *reinterpret_cast<const int4*>(g_ssrc + k);
        int4 sb = *reinterpret_cast<const int4*>(g_ssrc + k + 4);
        uint4 u0 = __ldg(&h[(size_t)sa.x * 8 + j]);
        uint4 u1 = __ldg(&h[(size_t)sa.y * 8 + j]);
        uint4 u2 = __ldg(&h[(size_t)sa.z * 8 + j]);
        uint4 u3 = __ldg(&h[(size_t)sa.w * 8 + j]);
        uint4 u4 = __ldg(&h[(size_t)sb.x * 8 + j]);
        uint4 u5 = __ldg(&h[(size_t)sb.y * 8 + j]);
        uint4 u6 = __ldg(&h[(size_t)sb.z * 8 + j]);
        uint4 u7 = __ldg(&h[(size_t)sb.w * 8 + j]);
        acc_bf8(acc, u0); acc_bf8(acc, u1); acc_bf8(acc, u2); acc_bf8(acc, u3);
        acc_bf8(acc, u4); acc_bf8(acc, u5); acc_bf8(acc, u6); acc_bf8(acc, u7);
    }
    for (; k + 4 <= end; k += 4) {
        int4 sa = *reinterpret_cast<const int4*>(g_ssrc + k);
        uint4 u0 = __ldg(&h[(size_t)sa.x * 8 + j]);
        uint4 u1 = __ldg(&h[(size_t)sa.y * 8 + j]);
        uint4 u2 = __ldg(&h[(size_t)sa.z * 8 + j]);
        uint4 u3 = __ldg(&h[(size_t)sa.w * 8 + j]);
        acc_bf8(acc, u0); acc_bf8(acc, u1); acc_bf8(acc, u2); acc_bf8(acc, u3);
    }
    for (; k < end; k++)
        acc_bf8(acc, __ldg(&h[(size_t)g_ssrc[k] * 8 + j]));

    float di = g_dinv[d];
    float y[8];
#pragma unroll
    for (int i = 0; i < 8; i++)
        y[i] = fmaxf(fmaf(di, acc[i], b2[j * 8 + i]), 0.0f);
    float* p = g_sums + (size_t)batch[d] * HDIM + j * 8;
    asm volatile(
        "{\n\t"
        ".reg .u64 ga;\n\t"
        "cvta.to.global.u64 ga, %0;\n\t"
        "red.global.add.v4.f32 [ga], {%1, %2, %3, %4};\n\t"
        "red.global.add.v4.f32 [ga+16], {%5, %6, %7, %8};\n\t"
        "}"
        :: "l"(p), "f"(y[0]), "f"(y[1]), "f"(y[2]), "f"(y[3]),
           "f"(y[4]), "f"(y[5]), "f"(y[6]), "f"(y[7]) : "memory");
}

// --------------------------------------------------- final
__global__ void final_kernel(const float* __restrict__ Wl, const float* __restrict__ bl,
                             float* __restrict__ out, int b_cnt) {
    int t = blockIdx.x * blockDim.x + threadIdx.x;
    if (t >= b_cnt * 2) return;
    int b = t >> 1, c = t & 1;
    float cnt = fmaxf(g_cnt[b], 1.0f);
    float acc = 0.0f;
#pragma unroll
    for (int k = 0; k < HDIM; k++) acc = fmaf(g_sums[b * HDIM + k], Wl[k * 2 + c], acc);
    out[b * 2 + c] = acc / cnt + bl[c];
}

// ====================================================================
extern "C" void kernel_launch(void* const* d_in, const int* in_sizes, int n_in,
                              void* d_out, int out_size) {
    const float* x     = (const float*)d_in[0];
    const int*   ei    = (const int*)d_in[1];
    const int*   batch = (const int*)d_in[2];
    const float* W1    = (const float*)d_in[3];
    const float* b1    = (const float*)d_in[4];
    const float* W2    = (const float*)d_in[5];
    const float* b2    = (const float*)d_in[6];
    const float* Wl    = (const float*)d_in[7];
    const float* bl    = (const float*)d_in[8];
    float* out = (float*)d_out;

    int n = in_sizes[0] / FIN;        // 100000
    int e = in_sizes[1] / 2;          // 3200000
    int b = out_size / 2;             // 256
    int nb = (n + 255) / 256;

    // One-time host-side stream/event setup (no device memory involved).
    static cudaStream_t s_side = nullptr;
    static cudaEvent_t ev_fork = nullptr, ev_join = nullptr;
    if (s_side == nullptr) {
        cudaStreamCreateWithFlags(&s_side, cudaStreamNonBlocking);
        cudaEventCreateWithFlags(&ev_fork, cudaEventDisableTiming);
        cudaEventCreateWithFlags(&ev_join, cudaEventDisableTiming);
    }

    // Fork: CSR prep chain on side stream; gemm1 (dinv-free) on main stream.
    cudaEventRecord(ev_fork, 0);
    cudaStreamWaitEvent(s_side, ev_fork, 0);

    init_kernel<<<(n + 255) / 256, 256, 0, s_side>>>(n, b);
    hist_kernel<<<(e + 255) / 256, 256, 0, s_side>>>(ei, e);
    scanA_kernel<<<nb, 256, 0, s_side>>>(n);
    scanB_kernel<<<1, 512, 0, s_side>>>(nb);
    scanC_kernel<<<nb, 256, 0, s_side>>>(batch, n, e);
    place_kernel<<<(e + 255) / 256, 256, 0, s_side>>>(ei, e);
    cudaEventRecord(ev_join, s_side);

    // gemm1 reads only x and W1 — independent of the side stream.
    gemm1_kernel<<<(n + G1_BM - 1) / G1_BM, 256>>>(x, W1, n);

    // Join: everything after needs CSR + dinv.
    cudaStreamWaitEvent(0, ev_join, 0);
    {
        long long threads = (long long)n * 8;
        scale_h1_kernel<<<(int)((threads + 255) / 256), 256>>>(n);
        gather1_kernel<<<(int)((threads + 255) / 256), 256>>>(n);
    }
    gemm2_kernel<<<(n + G2_BM - 1) / G2_BM, 256>>>(W2, b1, n);
    {
        long long threads = (long long)n * 8;
        gather2_pool_kernel<<<(int)((threads + 255) / 256), 256>>>(b2, batch, n);
    }
    final_kernel<<<(b * 2 + 255) / 256, 256>>>(Wl, bl, out, b);
}